// round 15
// baseline (speedup 1.0000x reference)
#include <cuda_runtime.h>
#include <cuda_bf16.h>
#include <cstdint>
#include <math.h>

#define BB 4
#define SS 1024
#define DD 1024
#define HH 16
#define DKK 64

// ---------------------------------------------------------------------------
// Portable PTX helpers (sm_80+: mma.sync, ldmatrix, cp.async)
// ---------------------------------------------------------------------------
__device__ __forceinline__ uint32_t smem_u32(const void* p) {
    uint32_t a;
    asm("{ .reg .u64 t; cvta.to.shared.u64 t, %1; cvt.u32.u64 %0, t; }" : "=r"(a) : "l"(p));
    return a;
}
#define CPASYNC16(dst, src) \
    asm volatile("cp.async.cg.shared.global [%0], [%1], 16;" :: "r"(dst), "l"(src) : "memory")
#define CPCOMMIT() asm volatile("cp.async.commit_group;" ::: "memory")
#define CPWAITG(n) asm volatile("cp.async.wait_group %0;" :: "n"(n) : "memory")

#define LDSM4(r0, r1, r2, r3, addr) \
    asm volatile("ldmatrix.sync.aligned.m8n8.x4.shared.b16 {%0,%1,%2,%3}, [%4];" \
                 : "=r"(r0), "=r"(r1), "=r"(r2), "=r"(r3) : "r"(addr))

#define MMA16816(c, a, b) \
    asm volatile("mma.sync.aligned.m16n8k16.row.col.f32.bf16.bf16.f32 " \
                 "{%0,%1,%2,%3},{%4,%5,%6,%7},{%8,%9},{%0,%1,%2,%3};" \
                 : "+f"((c)[0]), "+f"((c)[1]), "+f"((c)[2]), "+f"((c)[3]) \
                 : "r"((a)[0]), "r"((a)[1]), "r"((a)[2]), "r"((a)[3]), \
                   "r"((b)[0]), "r"((b)[1]))

#define MMA16832(c, a, b) \
    asm volatile("mma.sync.aligned.m16n8k32.row.col.s32.s8.s8.s32 " \
                 "{%0,%1,%2,%3},{%4,%5,%6,%7},{%8,%9},{%0,%1,%2,%3};" \
                 : "+r"((c)[0]), "+r"((c)[1]), "+r"((c)[2]), "+r"((c)[3]) \
                 : "r"((a)[0]), "r"((a)[1]), "r"((a)[2]), "r"((a)[3]), \
                   "r"((b)[0]), "r"((b)[1]))

// ---------------------------------------------------------------------------
// Scratch (static device globals)
// ---------------------------------------------------------------------------
__device__ __nv_bfloat16 g_WGhi[DD * DD];
__device__ __nv_bfloat16 g_WGlo[DD * DD];
__device__ __nv_bfloat16 g_WkThi[DD * DD];
__device__ __nv_bfloat16 g_WkTlo[DD * DD];
__device__ float  g_WGKT[DD * DD];         // fp32 WGK^T (GEMM1 out)
__device__ char   g_Xq[BB * SS * 2048];    // per row: 16 chunks x [A1 64B | A2 64B]
__device__ char   g_Wq[DD * 2048];
__device__ float  g_sA[BB * SS];
__device__ float  g_sB[DD];
__device__ float  g_biask[DD];
__device__ float  g_g0[BB * DD];
__device__ float  g_q0[BB * DD];
__device__ float  g_scores[BB * HH * SS];
__device__ float  g_row0[BB * HH * SS];
__device__ float2 g_tab[SS * 32];          // (cos, sin) for pos t, freq p

// ---------------------------------------------------------------------------
// RoPE sincos table
// ---------------------------------------------------------------------------
__global__ void tab_kernel(float2* __restrict__ tab)
{
    int idx = blockIdx.x * 256 + threadIdx.x;   // 32768 total
    int t = idx >> 5, p = idx & 31;
    float inv = exp2f(-(float)p * 0.41524101186092029f);  // 10000^(-p/32)
    float sn, cs;
    sincosf((float)t * inv, &sn, &cs);
    tab[idx] = make_float2(cs, sn);
}

// ---------------------------------------------------------------------------
// fp32 -> bf16 hi/lo split (weights only now)
// ---------------------------------------------------------------------------
__global__ void split_kernel(const float4* __restrict__ in,
                             __nv_bfloat162* __restrict__ hi,
                             __nv_bfloat162* __restrict__ lo, int n4)
{
    int i = blockIdx.x * 256 + threadIdx.x;
    if (i >= n4) return;
    float4 v = in[i];
    __nv_bfloat16 hx = __float2bfloat16(v.x), hy = __float2bfloat16(v.y);
    __nv_bfloat16 hz = __float2bfloat16(v.z), hw = __float2bfloat16(v.w);
    __nv_bfloat162 a, b;
    a.x = hx; a.y = hy; b.x = hz; b.y = hw;
    hi[2 * i] = a; hi[2 * i + 1] = b;
    __nv_bfloat162 c, d;
    c.x = __float2bfloat16(v.x - __bfloat162float(hx));
    c.y = __float2bfloat16(v.y - __bfloat162float(hy));
    d.x = __float2bfloat16(v.z - __bfloat162float(hz));
    d.y = __float2bfloat16(v.w - __bfloat162float(hw));
    lo[2 * i] = c; lo[2 * i + 1] = d;
}

// Transpose + split: out[c][r] = in[r][c], 1024x1024
__global__ void transpose_split_kernel(const float* __restrict__ in,
                                       __nv_bfloat16* __restrict__ thi,
                                       __nv_bfloat16* __restrict__ tlo)
{
    __shared__ float t[32][33];
    int c0 = blockIdx.x * 32, r0 = blockIdx.y * 32;
    int tx = threadIdx.x, ty = threadIdx.y;
#pragma unroll
    for (int k = 0; k < 4; k++)
        t[ty + 8 * k][tx] = in[(size_t)(r0 + ty + 8 * k) * 1024 + c0 + tx];
    __syncthreads();
#pragma unroll
    for (int k = 0; k < 4; k++) {
        float v = t[tx][ty + 8 * k];
        __nv_bfloat16 h = __float2bfloat16(v);
        size_t o = (size_t)(c0 + ty + 8 * k) * 1024 + r0 + tx;
        thi[o] = h;
        tlo[o] = __float2bfloat16(v - __bfloat162float(h));
    }
}

// ---------------------------------------------------------------------------
// Per-row 2-level int8 quantization: x = s*(A1 + A2/128), s = rowmax/127.
// One block per row; layout: out[row][ch][0..63]=A1(k=64ch..), [64..127]=A2.
// ---------------------------------------------------------------------------
__global__ __launch_bounds__(256) void quant_rows(const float* __restrict__ in,
                                                  char* __restrict__ outq,
                                                  float* __restrict__ scales)
{
    __shared__ float red[8];
    __shared__ float sh_inv, sh_s;
    const int row = blockIdx.x;
    const int tid = threadIdx.x;
    float4 v = *(const float4*)(in + (size_t)row * 1024 + tid * 4);
    float m = fmaxf(fmaxf(fabsf(v.x), fabsf(v.y)), fmaxf(fabsf(v.z), fabsf(v.w)));
#pragma unroll
    for (int o = 16; o; o >>= 1) m = fmaxf(m, __shfl_xor_sync(0xffffffffu, m, o));
    if ((tid & 31) == 0) red[tid >> 5] = m;
    __syncthreads();
    if (tid == 0) {
        float mm = red[0];
#pragma unroll
        for (int i = 1; i < 8; i++) mm = fmaxf(mm, red[i]);
        float s = fmaxf(mm, 1e-20f) / 127.0f;
        sh_s = s;
        sh_inv = 1.0f / s;
    }
    __syncthreads();
    if (tid == 0) scales[row] = sh_s;
    const float inv = sh_inv;

    float xs0 = v.x * inv, xs1 = v.y * inv, xs2 = v.z * inv, xs3 = v.w * inv;
    float a10 = rintf(xs0), a11 = rintf(xs1), a12 = rintf(xs2), a13 = rintf(xs3);
    char4 q1 = make_char4((char)(int)a10, (char)(int)a11, (char)(int)a12, (char)(int)a13);
    char4 q2 = make_char4((char)(int)rintf((xs0 - a10) * 128.0f),
                          (char)(int)rintf((xs1 - a11) * 128.0f),
                          (char)(int)rintf((xs2 - a12) * 128.0f),
                          (char)(int)rintf((xs3 - a13) * 128.0f));
    int k0 = tid * 4;
    int ch = k0 >> 6, pos = k0 & 63;
    char* dst = outq + (size_t)row * 2048 + ch * 128 + pos;
    *(char4*)dst = q1;
    *(char4*)(dst + 64) = q2;
}

// ---------------------------------------------------------------------------
// Fast GEMV: 1 col/lane, 32 cols/block, grid (32, nb).
// ---------------------------------------------------------------------------
__global__ __launch_bounds__(256) void gemv_fast(const float* __restrict__ x,
                                                 const float* __restrict__ W,
                                                 const float* __restrict__ bv,
                                                 float* __restrict__ out,
                                                 long long xstride)
{
    __shared__ float xs[1024];
    __shared__ float red[8][32];
    const int b = blockIdx.y;
    const int tid = threadIdx.x;
    const int lane = tid & 31, ig = tid >> 5;
    const float* xr = x + (long long)b * xstride;
    for (int i = tid; i < 1024; i += 256) xs[i] = xr[i];
    __syncthreads();

    const int j = blockIdx.x * 32 + lane;
    const float* Wp = W + (long long)(ig * 128) * 1024 + j;
    float a0 = 0.f;
#pragma unroll 8
    for (int i = 0; i < 128; i++)
        a0 = fmaf(xs[ig * 128 + i], Wp[(long long)i * 1024], a0);
    red[ig][lane] = a0;
    __syncthreads();
    if (tid < 32) {
        int jo = blockIdx.x * 32 + tid;
        float s = bv[jo];
#pragma unroll
        for (int g = 0; g < 8; g++) s += red[g][tid];
        out[b * 1024 + jo] = s;
    }
}

// ---------------------------------------------------------------------------
// GEMM1 (bf16 3-term): C[m,n] = sum_k A[m,k]*B[n,k], fp32 out.
// CTA 64x128, 8 warps, 2-stage cp.async, SW128.
// ---------------------------------------------------------------------------
__global__ __launch_bounds__(256) void mmagemm1(
    const __nv_bfloat16* __restrict__ Ahi, const __nv_bfloat16* __restrict__ Alo,
    const __nv_bfloat16* __restrict__ Bhi, const __nv_bfloat16* __restrict__ Blo,
    float* __restrict__ Cf)
{
    constexpr int MT = 2;
    constexpr int AIT = 2;
    constexpr uint32_t STAGE = (64 + 128) * 128;   // 24576
    constexpr uint32_t BOFF = 64 * 128;

    extern __shared__ char dyn[];
    uint32_t dynb = smem_u32(dyn);
    const uint32_t sbase = (dynb + 1023) & ~1023u;

    const int tid = threadIdx.x;
    const int wid = tid >> 5, lane = tid & 31;
    const int gid = lane >> 2, tig = lane & 3;
    const int m0 = blockIdx.y * 64, n0 = blockIdx.x * 128;
    const int wm = (wid >> 2) * 32;
    const int wn = (wid & 3) * 32;

    const __nv_bfloat16* aSrc[AIT];
    const __nv_bfloat16* bSrc[4];
    uint32_t aDst[AIT], bDst[4];
#pragma unroll
    for (int it = 0; it < AIT; it++) {
        int ix = it * 256 + tid;
        int r = ix >> 3, seg = ix & 7;
        const __nv_bfloat16* ah = (seg < 4) ? Ahi : Alo;
        aSrc[it] = ah + (size_t)(m0 + r) * 1024 + (seg & 3) * 8;
        aDst[it] = sbase + r * 128 + ((seg * 16) ^ ((r & 7) << 4));
    }
#pragma unroll
    for (int it = 0; it < 4; it++) {
        int ix = it * 256 + tid;
        int r = ix >> 3, seg = ix & 7;
        const __nv_bfloat16* bh = (seg < 4) ? Bhi : Blo;
        bSrc[it] = bh + (size_t)(n0 + r) * 1024 + (seg & 3) * 8;
        bDst[it] = sbase + BOFF + r * 128 + ((seg * 16) ^ ((r & 7) << 4));
    }

    const uint32_t xorv = (lane & 7) << 4;
    const uint32_t ksel = (lane >> 4) * 16;
    uint32_t aRow[MT], bRow[2];
#pragma unroll
    for (int mt = 0; mt < MT; mt++) aRow[mt] = (wm + mt * 16 + (lane & 15)) * 128;
#pragma unroll
    for (int ng = 0; ng < 2; ng++)  bRow[ng] = BOFF + (wn + ng * 16 + (lane & 15)) * 128;

    float acc[MT][4][4];
#pragma unroll
    for (int mt = 0; mt < MT; mt++)
#pragma unroll
        for (int nt = 0; nt < 4; nt++)
#pragma unroll
            for (int i = 0; i < 4; i++) acc[mt][nt][i] = 0.f;

#pragma unroll
    for (int it = 0; it < AIT; it++) CPASYNC16(aDst[it], aSrc[it]);
#pragma unroll
    for (int it = 0; it < 4; it++)   CPASYNC16(bDst[it], bSrc[it]);
    CPCOMMIT();

#pragma unroll 1
    for (int ch = 0; ch < 32; ch++) {
        const int s = ch & 1;
        if (ch < 31) {
            const uint32_t so = (uint32_t)(s ^ 1) * STAGE;
            const int ko = (ch + 1) * 32;
#pragma unroll
            for (int it = 0; it < AIT; it++) CPASYNC16(aDst[it] + so, aSrc[it] + ko);
#pragma unroll
            for (int it = 0; it < 4; it++)   CPASYNC16(bDst[it] + so, bSrc[it] + ko);
            CPCOMMIT();
            CPWAITG(1);
        } else {
            CPWAITG(0);
        }
        __syncthreads();

        const uint32_t As = sbase + (uint32_t)s * STAGE;
#pragma unroll
        for (int ks = 0; ks < 2; ks++) {
            const uint32_t khi = (ks * 32 + ksel) ^ xorv;
            const uint32_t klo = (64 + ks * 32 + ksel) ^ xorv;
            uint32_t bh[4][2], bl[4][2];
#pragma unroll
            for (int ng = 0; ng < 2; ng++) {
                uint32_t r0, r1, r2, r3;
                LDSM4(r0, r1, r2, r3, As + bRow[ng] + khi);
                bh[2 * ng][0] = r0; bh[2 * ng][1] = r2;
                bh[2 * ng + 1][0] = r1; bh[2 * ng + 1][1] = r3;
                LDSM4(r0, r1, r2, r3, As + bRow[ng] + klo);
                bl[2 * ng][0] = r0; bl[2 * ng][1] = r2;
                bl[2 * ng + 1][0] = r1; bl[2 * ng + 1][1] = r3;
            }
#pragma unroll
            for (int mt = 0; mt < MT; mt++) {
                uint32_t ah[4], al[4];
                LDSM4(ah[0], ah[1], ah[2], ah[3], As + aRow[mt] + khi);
                LDSM4(al[0], al[1], al[2], al[3], As + aRow[mt] + klo);
#pragma unroll
                for (int nt = 0; nt < 4; nt++) {
                    MMA16816(acc[mt][nt], ah, bh[nt]);
                    MMA16816(acc[mt][nt], ah, bl[nt]);
                    MMA16816(acc[mt][nt], al, bh[nt]);
                }
            }
        }
        __syncthreads();
    }

#pragma unroll
    for (int mt = 0; mt < MT; mt++) {
#pragma unroll
        for (int half = 0; half < 2; half++) {
            int row = m0 + wm + mt * 16 + gid + half * 8;
#pragma unroll
            for (int nt = 0; nt < 4; nt++) {
                int col = n0 + wn + nt * 8 + 2 * tig;
                float2 o;
                o.x = acc[mt][nt][half * 2];
                o.y = acc[mt][nt][half * 2 + 1];
                *(float2*)(Cf + (size_t)row * 1024 + col) = o;
            }
        }
    }
}

// ---------------------------------------------------------------------------
// GEMM2 (int8 2-level): scores[b,h,t] = q0[b,h,:] . rope_t(sA*sB*acc + bias)/8
// CTA 128x128, 8 warps, K = 16 chunks of 64 int8, 2-stage cp.async, SW128.
// Value = sA[row]*sB[col]*(acc11 + accX/128). Halves MMA instruction count.
// ---------------------------------------------------------------------------
__global__ __launch_bounds__(256) void mmagemm8(
    const char* __restrict__ Aq, const float* __restrict__ sAv,
    const char* __restrict__ Bq, const float* __restrict__ sBv,
    const float* __restrict__ bias, const float* __restrict__ q0,
    const float2* __restrict__ tab, float* __restrict__ scores)
{
    constexpr uint32_t STAGE = 256 * 128;   // 32768 (A 16K + B 16K)
    constexpr uint32_t BOFF = 128 * 128;

    extern __shared__ char dyn[];
    uint32_t dynb = smem_u32(dyn);
    const uint32_t sbase = (dynb + 1023) & ~1023u;

    const int tid = threadIdx.x;
    const int wid = tid >> 5, lane = tid & 31;
    const int gid = lane >> 2, tig = lane & 3;
    const int m0 = blockIdx.y * 128, n0 = blockIdx.x * 128;
    const int wm = (wid >> 2) * 64;
    const int wn = (wid & 3) * 32;

    const char* aSrc[4];
    const char* bSrc[4];
    uint32_t aDst[4], bDst[4];
#pragma unroll
    for (int it = 0; it < 4; it++) {
        int ix = it * 256 + tid;
        int r = ix >> 3, seg = ix & 7;
        aSrc[it] = Aq + (size_t)(m0 + r) * 2048 + seg * 16;
        aDst[it] = sbase + r * 128 + ((seg * 16) ^ ((r & 7) << 4));
        bSrc[it] = Bq + (size_t)(n0 + r) * 2048 + seg * 16;
        bDst[it] = sbase + BOFF + r * 128 + ((seg * 16) ^ ((r & 7) << 4));
    }

    const uint32_t xorv = (lane & 7) << 4;
    const uint32_t ksel = (lane >> 4) * 16;
    uint32_t aRow[4], bRow[2];
#pragma unroll
    for (int mt = 0; mt < 4; mt++) aRow[mt] = (wm + mt * 16 + (lane & 15)) * 128;
#pragma unroll
    for (int ng = 0; ng < 2; ng++)  bRow[ng] = BOFF + (wn + ng * 16 + (lane & 15)) * 128;

    int acc11[4][4][4], accX[4][4][4];
#pragma unroll
    for (int mt = 0; mt < 4; mt++)
#pragma unroll
        for (int nt = 0; nt < 4; nt++)
#pragma unroll
            for (int i = 0; i < 4; i++) { acc11[mt][nt][i] = 0; accX[mt][nt][i] = 0; }

    // prologue: chunk 0 -> stage 0
#pragma unroll
    for (int it = 0; it < 4; it++) {
        CPASYNC16(aDst[it], aSrc[it]);
        CPASYNC16(bDst[it], bSrc[it]);
    }
    CPCOMMIT();

#pragma unroll 1
    for (int ch = 0; ch < 16; ch++) {
        const int s = ch & 1;
        if (ch < 15) {
            const uint32_t so = (uint32_t)(s ^ 1) * STAGE;
            const int ko = (ch + 1) * 128;
#pragma unroll
            for (int it = 0; it < 4; it++) {
                CPASYNC16(aDst[it] + so, aSrc[it] + ko);
                CPASYNC16(bDst[it] + so, bSrc[it] + ko);
            }
            CPCOMMIT();
            CPWAITG(1);
        } else {
            CPWAITG(0);
        }
        __syncthreads();

        const uint32_t As = sbase + (uint32_t)s * STAGE;
#pragma unroll
        for (int ks = 0; ks < 2; ks++) {
            const uint32_t k1 = (ks * 32 + ksel) ^ xorv;        // A1/B1 bytes
            const uint32_t k2 = (64 + ks * 32 + ksel) ^ xorv;   // A2/B2 bytes
            uint32_t b1[4][2], b2[4][2];
#pragma unroll
            for (int ng = 0; ng < 2; ng++) {
                uint32_t r0, r1, r2, r3;
                LDSM4(r0, r1, r2, r3, As + bRow[ng] + k1);
                b1[2 * ng][0] = r0; b1[2 * ng][1] = r2;
                b1[2 * ng + 1][0] = r1; b1[2 * ng + 1][1] = r3;
                LDSM4(r0, r1, r2, r3, As + bRow[ng] + k2);
                b2[2 * ng][0] = r0; b2[2 * ng][1] = r2;
                b2[2 * ng + 1][0] = r1; b2[2 * ng + 1][1] = r3;
            }
#pragma unroll
            for (int mt = 0; mt < 4; mt++) {
                uint32_t a1[4], a2[4];
                LDSM4(a1[0], a1[1], a1[2], a1[3], As + aRow[mt] + k1);
                LDSM4(a2[0], a2[1], a2[2], a2[3], As + aRow[mt] + k2);
#pragma unroll
                for (int nt = 0; nt < 4; nt++) {
                    MMA16832(acc11[mt][nt], a1, b1[nt]);
                    MMA16832(accX[mt][nt], a1, b2[nt]);
                    MMA16832(accX[mt][nt], a2, b1[nt]);
                }
            }
        }
        __syncthreads();
    }

    // ---- fused epilogue: dequant + bias + rope + q-dot -> scores -----------
    const int b = m0 >> 10;
    const int tbase = m0 & 1023;
    float2 bb[4], qv[4], sb[4];
    const float2* tabp[4];
#pragma unroll
    for (int nt = 0; nt < 4; nt++) {
        int col = n0 + wn + nt * 8 + 2 * tig;
        bb[nt] = *(const float2*)(bias + col);
        qv[nt] = *(const float2*)(q0 + b * 1024 + col);
        sb[nt] = *(const float2*)(sBv + col);
        tabp[nt] = tab + ((col & 63) >> 1);
    }
    float* spart = (float*)dyn;      // [128][4] partials
#pragma unroll
    for (int mt = 0; mt < 4; mt++) {
#pragma unroll
        for (int half = 0; half < 2; half++) {
            int rl = wm + mt * 16 + gid + half * 8;      // local row
            int t = tbase + rl;
            float sar = sAv[m0 + rl];
            float p_acc = 0.f;
#pragma unroll
            for (int nt = 0; nt < 4; nt++) {
                float2 cssn = tabp[nt][t * 32];
                float f0 = (float)acc11[mt][nt][half * 2]
                         + (float)accX[mt][nt][half * 2] * 0.0078125f;
                float f1 = (float)acc11[mt][nt][half * 2 + 1]
                         + (float)accX[mt][nt][half * 2 + 1] * 0.0078125f;
                float v0 = f0 * (sar * sb[nt].x) + bb[nt].x;
                float v1 = f1 * (sar * sb[nt].y) + bb[nt].y;
                float kw0 = v0 * cssn.x - v1 * cssn.y;
                float kw1 = v1 * cssn.x + v0 * cssn.y;
                p_acc = fmaf(qv[nt].x, kw0, p_acc);
                p_acc = fmaf(qv[nt].y, kw1, p_acc);
            }
            p_acc += __shfl_xor_sync(0xffffffffu, p_acc, 1);
            p_acc += __shfl_xor_sync(0xffffffffu, p_acc, 2);
            if (tig == 0) spart[rl * 4 + (wn >> 5)] = p_acc;
        }
    }
    __syncthreads();
    if (tid < 128) {
        int t = tbase + tid;
        float s0 = (spart[tid * 4 + 0] + spart[tid * 4 + 1]) * 0.125f;
        float s1 = (spart[tid * 4 + 2] + spart[tid * 4 + 3]) * 0.125f;
        int h0 = n0 >> 6;
        scores[((b * 16 + h0)     << 10) + t] = s0;
        scores[((b * 16 + h0 + 1) << 10) + t] = s1;
    }
}

// ---------------------------------------------------------------------------
// Masked softmax over scores rows -> row0. grid 64 (b*16+h), 256 threads.
// ---------------------------------------------------------------------------
__global__ __launch_bounds__(256) void softmax_kernel(const int* __restrict__ mask,
                                                      const float* __restrict__ scores,
                                                      float* __restrict__ row0)
{
    int bh = blockIdx.x;
    int b = bh >> 4;
    __shared__ float sc[1024];
    __shared__ float red[8];
    __shared__ float bc;
    int tid = threadIdx.x;

    float lmax = -3.4e38f;
#pragma unroll
    for (int it = 0; it < 4; it++) {
        int t = it * 256 + tid;
        float s = scores[(bh << 10) + t];
        s = (mask[b * 1024 + t] == 0) ? -1e9f : s;
        sc[t] = s;
        lmax = fmaxf(lmax, s);
    }
#pragma unroll
    for (int o = 16; o; o >>= 1) lmax = fmaxf(lmax, __shfl_xor_sync(0xffffffffu, lmax, o));
    if ((tid & 31) == 0) red[tid >> 5] = lmax;
    __syncthreads();
    if (tid == 0) {
        float m = red[0];
        for (int i = 1; i < 8; i++) m = fmaxf(m, red[i]);
        bc = m;
    }
    __syncthreads();
    float gmax = bc;

    float lsum = 0.f;
#pragma unroll
    for (int it = 0; it < 4; it++) {
        int t = it * 256 + tid;
        float e = expf(sc[t] - gmax);
        sc[t] = e;
        lsum += e;
    }
#pragma unroll
    for (int o = 16; o; o >>= 1) lsum += __shfl_xor_sync(0xffffffffu, lsum, o);
    if ((tid & 31) == 0) red[tid >> 5] = lsum;
    __syncthreads();
    if (tid == 0) {
        float s = 0.f;
        for (int i = 0; i < 8; i++) s += red[i];
        bc = 1.f / s;
    }
    __syncthreads();
    float invs = bc;
#pragma unroll
    for (int it = 0; it < 4; it++) {
        int t = it * 256 + tid;
        row0[(bh << 10) + t] = sc[t] * invs;
    }
}

// ---------------------------------------------------------------------------
// Conv1d(16 -> 1024, k=3, pad=1) + bias + relu
// ---------------------------------------------------------------------------
#define OPB 16
__global__ __launch_bounds__(256) void conv_kernel(const float* __restrict__ cw,
                                                   const float* __restrict__ cb,
                                                   const float* __restrict__ row0,
                                                   float* __restrict__ out)
{
    int lc = blockIdx.x, og = blockIdx.y, b = blockIdx.z;
    __shared__ float tile[16][264];
    __shared__ float ws[OPB * 48];
    __shared__ float wb[OPB];
    int tid = threadIdx.x;

    for (int idx = tid; idx < OPB * 48; idx += 256) {
        int o = og * OPB + idx / 48;
        ws[idx] = cw[o * 48 + (idx % 48)];
    }
    if (tid < OPB) wb[tid] = cb[og * OPB + tid];
    for (int idx = tid; idx < 16 * 258; idx += 256) {
        int c = idx / 258, x = idx % 258;
        int l = lc * 256 - 1 + x;
        tile[c][x] = (l >= 0 && l < SS) ? row0[((long long)(b * 16 + c)) * SS + l] : 0.f;
    }
    __syncthreads();

    float acc[OPB];
#pragma unroll
    for (int o = 0; o < OPB; o++) acc[o] = wb[o];
#pragma unroll
    for (int c = 0; c < 16; c++) {
        float r0 = tile[c][tid], r1 = tile[c][tid + 1], r2 = tile[c][tid + 2];
#pragma unroll
        for (int o = 0; o < OPB; o++) {
            acc[o] = fmaf(r0, ws[o * 48 + c * 3],     acc[o]);
            acc[o] = fmaf(r1, ws[o * 48 + c * 3 + 1], acc[o]);
            acc[o] = fmaf(r2, ws[o * 48 + c * 3 + 2], acc[o]);
        }
    }
    int l = lc * 256 + tid;
#pragma unroll
    for (int o = 0; o < OPB; o++)
        out[((long long)(b * 1024 + og * OPB + o)) * SS + l] = fmaxf(acc[o], 0.f);
}

// ---------------------------------------------------------------------------
extern "C" void kernel_launch(void* const* d_in, const int* in_sizes, int n_in,
                              void* d_out, int out_size)
{
    const float* X    = (const float*)d_in[0];
    const int*   mask = (const int*)d_in[1];
    const float* W_G  = (const float*)d_in[2];
    const float* b_G  = (const float*)d_in[3];
    const float* Wq   = (const float*)d_in[4];
    const float* bq   = (const float*)d_in[5];
    const float* Wk   = (const float*)d_in[6];
    const float* bk   = (const float*)d_in[7];
    const float* cw   = (const float*)d_in[8];
    const float* cb   = (const float*)d_in[9];
    float* out = (float*)d_out;

    __nv_bfloat16 *pWGhi, *pWGlo, *pWkThi, *pWkTlo;
    float *pWGKT, *psA, *psB, *pbiask, *pg0, *pq0, *pscores, *prow0;
    char *pXq, *pWq;
    float2* ptab;
    cudaGetSymbolAddress((void**)&pWGhi,   g_WGhi);
    cudaGetSymbolAddress((void**)&pWGlo,   g_WGlo);
    cudaGetSymbolAddress((void**)&pWkThi,  g_WkThi);
    cudaGetSymbolAddress((void**)&pWkTlo,  g_WkTlo);
    cudaGetSymbolAddress((void**)&pWGKT,   g_WGKT);
    cudaGetSymbolAddress((void**)&pXq,     g_Xq);
    cudaGetSymbolAddress((void**)&pWq,     g_Wq);
    cudaGetSymbolAddress((void**)&psA,     g_sA);
    cudaGetSymbolAddress((void**)&psB,     g_sB);
    cudaGetSymbolAddress((void**)&pbiask,  g_biask);
    cudaGetSymbolAddress((void**)&pg0,     g_g0);
    cudaGetSymbolAddress((void**)&pq0,     g_q0);
    cudaGetSymbolAddress((void**)&pscores, g_scores);
    cudaGetSymbolAddress((void**)&prow0,   g_row0);
    cudaGetSymbolAddress((void**)&ptab,    g_tab);

    static int smem_set = 0;
    if (!smem_set) {
        cudaFuncSetAttribute(mmagemm1, cudaFuncAttributeMaxDynamicSharedMemorySize, 50176);
        cudaFuncSetAttribute(mmagemm8, cudaFuncAttributeMaxDynamicSharedMemorySize, 66560);
        smem_set = 1;
    }

    // RoPE table + small GEMVs (fp32-exact q0 / biask)
    tab_kernel<<<128, 256>>>(ptab);
    gemv_fast<<<dim3(32, 1), 256>>>(b_G, Wk, bk, pbiask, 0LL);
    gemv_fast<<<dim3(32, 4), 256>>>(X, W_G, b_G, pg0, (long long)SS * DD);
    gemv_fast<<<dim3(32, 4), 256>>>(pg0, Wq, bq, pq0, 1024LL);

    // Weight conversions (bf16 hi/lo for GEMM1)
    split_kernel<<<1024, 256>>>((const float4*)W_G, (__nv_bfloat162*)pWGhi,
                                (__nv_bfloat162*)pWGlo, DD * DD / 4);
    transpose_split_kernel<<<dim3(32, 32), dim3(32, 8)>>>(Wk, pWkThi, pWkTlo);

    // X int8 2-level quantization (replaces X bf16 split)
    quant_rows<<<BB * SS, 256>>>(X, pXq, psA);

    // GEMM1: WGK^T fp32 (A = Wk^T, B = W_G)
    mmagemm1<<<dim3(8, 16), 256, 50176>>>(pWkThi, pWkTlo, pWGhi, pWGlo, pWGKT);

    // WGKT int8 2-level quantization
    quant_rows<<<DD, 256>>>(pWGKT, pWq, psB);

    // GEMM2 (int8): scores = q0 . rope(sA*sB*(X @ WGK) + biask) / 8
    mmagemm8<<<dim3(8, 32), 256, 66560>>>(pXq, psA, pWq, psB,
                                          pbiask, pq0, ptab, pscores);

    softmax_kernel<<<64, 256>>>(mask, pscores, prow0);
    conv_kernel<<<dim3(4, 64, 4), 256>>>(cw, cb, prow0, out);
}